// round 1
// baseline (speedup 1.0000x reference)
#include <cuda_runtime.h>
#include <math.h>

#define KDIM 512
#define NBLOCKS 1184
#define NTHREADS 256
#define WARPS_PER_BLOCK (NTHREADS / 32)

// Deterministic per-block partial sums (no device allocation allowed).
__device__ double g_partials[NBLOCKS];

__global__ __launch_bounds__(NTHREADS) void sce_main_kernel(
    const float* __restrict__ input,
    const float* __restrict__ target,
    const float* __restrict__ weight,
    int n_rows)
{
    __shared__ float s_w[KDIM];
    __shared__ double s_warp[WARPS_PER_BLOCK];

    const int tid = threadIdx.x;
    // Stage weight vector in shared (2 KB), read K times per block afterwards.
    for (int i = tid; i < KDIM; i += NTHREADS) s_w[i] = weight[i];
    __syncthreads();

    const int warp = tid >> 5;
    const int lane = tid & 31;
    const int gwarp = blockIdx.x * WARPS_PER_BLOCK + warp;
    const int nwarps = NBLOCKS * WARPS_PER_BLOCK;

    double acc = 0.0;

    for (int row = gwarp; row < n_rows; row += nwarps) {
        const float4* xr = (const float4*)(input + (size_t)row * KDIM);
        const float4* tr = (const float4*)(target + (size_t)row * KDIM);

        float4 x[4], t[4];
        // 8 back-to-back 128B coalesced loads per warp — front-batched for MLP.
        #pragma unroll
        for (int j = 0; j < 4; j++) x[j] = xr[lane + 32 * j];
        #pragma unroll
        for (int j = 0; j < 4; j++) t[j] = tr[lane + 32 * j];

        // Row max
        float m = -INFINITY;
        #pragma unroll
        for (int j = 0; j < 4; j++) {
            m = fmaxf(m, fmaxf(fmaxf(x[j].x, x[j].y), fmaxf(x[j].z, x[j].w)));
        }
        #pragma unroll
        for (int o = 16; o > 0; o >>= 1)
            m = fmaxf(m, __shfl_xor_sync(0xFFFFFFFFu, m, o));

        // Fused: sum exp(x-m), sum t*w, sum t*w*x   (single register pass)
        float se = 0.f, tw = 0.f, twx = 0.f;
        #pragma unroll
        for (int j = 0; j < 4; j++) {
            const int c = (lane + 32 * j) * 4;
            const float w0 = s_w[c + 0], w1 = s_w[c + 1];
            const float w2 = s_w[c + 2], w3 = s_w[c + 3];
            se += __expf(x[j].x - m) + __expf(x[j].y - m)
                + __expf(x[j].z - m) + __expf(x[j].w - m);
            const float a0 = t[j].x * w0, a1 = t[j].y * w1;
            const float a2 = t[j].z * w2, a3 = t[j].w * w3;
            tw  += (a0 + a1) + (a2 + a3);
            twx += (a0 * x[j].x + a1 * x[j].y) + (a2 * x[j].z + a3 * x[j].w);
        }
        #pragma unroll
        for (int o = 16; o > 0; o >>= 1) {
            se  += __shfl_xor_sync(0xFFFFFFFFu, se, o);
            tw  += __shfl_xor_sync(0xFFFFFFFFu, tw, o);
            twx += __shfl_xor_sync(0xFFFFFFFFu, twx, o);
        }

        const float lse = m + __logf(se);
        acc += (double)(tw * lse - twx);   // per_row = sum t*w*(lse - x)
    }

    // All lanes hold identical acc after butterfly reductions; lane 0 publishes.
    if (lane == 0) s_warp[warp] = acc;
    __syncthreads();
    if (tid == 0) {
        double b = 0.0;
        #pragma unroll
        for (int i = 0; i < WARPS_PER_BLOCK; i++) b += s_warp[i];
        g_partials[blockIdx.x] = b;
    }
}

__global__ __launch_bounds__(NTHREADS) void sce_final_kernel(float* out, int n_rows)
{
    __shared__ double s[NTHREADS];
    double a = 0.0;
    for (int i = threadIdx.x; i < NBLOCKS; i += NTHREADS) a += g_partials[i];
    s[threadIdx.x] = a;
    __syncthreads();
    for (int o = NTHREADS / 2; o > 0; o >>= 1) {
        if (threadIdx.x < o) s[threadIdx.x] += s[threadIdx.x + o];
        __syncthreads();
    }
    if (threadIdx.x == 0) out[0] = (float)(s[0] / (double)n_rows);
}

extern "C" void kernel_launch(void* const* d_in, const int* in_sizes, int n_in,
                              void* d_out, int out_size)
{
    const float* input  = (const float*)d_in[0];
    const float* target = (const float*)d_in[1];
    const float* weight = (const float*)d_in[2];
    float* out = (float*)d_out;

    const int n_rows = in_sizes[0] / KDIM;

    sce_main_kernel<<<NBLOCKS, NTHREADS>>>(input, target, weight, n_rows);
    sce_final_kernel<<<1, NTHREADS>>>(out, n_rows);
}

// round 2
// speedup vs baseline: 1.0006x; 1.0006x over previous
#include <cuda_runtime.h>
#include <math.h>

#define KDIM 512
#define NBLOCKS 1184
#define NTHREADS 256
#define WARPS_PER_BLOCK (NTHREADS / 32)

// Deterministic per-block partial sums (no device allocation allowed).
__device__ double g_partials[NBLOCKS];
__device__ unsigned int g_count = 0;   // reset by the last block each call -> graph-replay safe

__global__ __launch_bounds__(NTHREADS) void sce_main_kernel(
    const float* __restrict__ input,
    const float* __restrict__ target,
    const float* __restrict__ weight,
    float* __restrict__ out,
    int n_rows)
{
    __shared__ float s_w[KDIM];
    __shared__ double s_warp[WARPS_PER_BLOCK];
    __shared__ bool s_last;

    const int tid = threadIdx.x;
    // Stage weight vector in shared (2 KB).
    for (int i = tid; i < KDIM; i += NTHREADS) s_w[i] = weight[i];
    __syncthreads();

    const int warp = tid >> 5;
    const int lane = tid & 31;
    const int gwarp = blockIdx.x * WARPS_PER_BLOCK + warp;
    const int nwarps = NBLOCKS * WARPS_PER_BLOCK;

    double acc = 0.0;

    for (int row = gwarp; row < n_rows; row += nwarps) {
        const float4* xr = (const float4*)(input + (size_t)row * KDIM);
        const float4* tr = (const float4*)(target + (size_t)row * KDIM);

        float4 x[4], t[4];
        // 8 back-to-back 128B coalesced loads per warp — front-batched for MLP.
        #pragma unroll
        for (int j = 0; j < 4; j++) x[j] = xr[lane + 32 * j];
        #pragma unroll
        for (int j = 0; j < 4; j++) t[j] = tr[lane + 32 * j];

        // Row max
        float m = -INFINITY;
        #pragma unroll
        for (int j = 0; j < 4; j++) {
            m = fmaxf(m, fmaxf(fmaxf(x[j].x, x[j].y), fmaxf(x[j].z, x[j].w)));
        }
        #pragma unroll
        for (int o = 16; o > 0; o >>= 1)
            m = fmaxf(m, __shfl_xor_sync(0xFFFFFFFFu, m, o));

        // Fused: sum exp(x-m), sum t*w, sum t*w*x (single register pass)
        float se = 0.f, tw = 0.f, twx = 0.f;
        #pragma unroll
        for (int j = 0; j < 4; j++) {
            const int c = (lane + 32 * j) * 4;
            const float w0 = s_w[c + 0], w1 = s_w[c + 1];
            const float w2 = s_w[c + 2], w3 = s_w[c + 3];
            se += __expf(x[j].x - m) + __expf(x[j].y - m)
                + __expf(x[j].z - m) + __expf(x[j].w - m);
            const float a0 = t[j].x * w0, a1 = t[j].y * w1;
            const float a2 = t[j].z * w2, a3 = t[j].w * w3;
            tw  += (a0 + a1) + (a2 + a3);
            twx += (a0 * x[j].x + a1 * x[j].y) + (a2 * x[j].z + a3 * x[j].w);
        }
        #pragma unroll
        for (int o = 16; o > 0; o >>= 1) {
            se  += __shfl_xor_sync(0xFFFFFFFFu, se, o);
            tw  += __shfl_xor_sync(0xFFFFFFFFu, tw, o);
            twx += __shfl_xor_sync(0xFFFFFFFFu, twx, o);
        }

        const float lse = m + __logf(se);
        acc += (double)(tw * lse - twx);   // per_row = sum t*w*(lse - x)
    }

    if (lane == 0) s_warp[warp] = acc;
    __syncthreads();
    if (tid == 0) {
        double b = 0.0;
        #pragma unroll
        for (int i = 0; i < WARPS_PER_BLOCK; i++) b += s_warp[i];
        g_partials[blockIdx.x] = b;
        // Publish partial to L2, then count this block done.
        __threadfence();
        unsigned int prev = atomicAdd(&g_count, 1u);
        s_last = (prev == NBLOCKS - 1);
    }
    __syncthreads();

    // Last block to finish performs the deterministic final reduction.
    if (s_last) {
        __shared__ double s_red[NTHREADS];
        double a = 0.0;
        for (int i = tid; i < NBLOCKS; i += NTHREADS)
            a += __ldcg(&g_partials[i]);   // L2 read — sees fenced writes
        s_red[tid] = a;
        __syncthreads();
        for (int o = NTHREADS / 2; o > 0; o >>= 1) {
            if (tid < o) s_red[tid] += s_red[tid + o];
            __syncthreads();
        }
        if (tid == 0) {
            out[0] = (float)(s_red[0] / (double)n_rows);
            g_count = 0;          // reset for the next (graph-replayed) call
            __threadfence();
        }
    }
}

extern "C" void kernel_launch(void* const* d_in, const int* in_sizes, int n_in,
                              void* d_out, int out_size)
{
    const float* input  = (const float*)d_in[0];
    const float* target = (const float*)d_in[1];
    const float* weight = (const float*)d_in[2];
    float* out = (float*)d_out;

    const int n_rows = in_sizes[0] / KDIM;

    sce_main_kernel<<<NBLOCKS, NTHREADS>>>(input, target, weight, out, n_rows);
}